// round 3
// baseline (speedup 1.0000x reference)
#include <cuda_runtime.h>
#include <math.h>

#define BB 64
#define NN 16800
#define CC 21
#define CHUNK 512
#define SS 33          // ceil(16800/512)
#define FP32_EPS 1.1920928955078125e-07f

// scratch (no cudaMalloc allowed)
__device__ unsigned int g_bits[BB * NN];      // labels_neg as fp32 bits (all >= +0)
__device__ float g_part_lb[BB * SS];          // partial sum pos*smoothl1
__device__ float g_part_cp[BB * SS];          // partial sum pos*ce
__device__ int   g_part_pn[BB * SS];          // partial pos count
__device__ float g_batch[BB * 3];             // per-batch (total, bbox, label)

__device__ __forceinline__ float sl1f(float d) {
    float a = fabsf(d);
    return a < 1.0f ? 0.5f * d * d : a - 0.5f;
}

// ---------------------------------------------------------------------------
// K1: stream everything once. One block = one 512-anchor chunk of one batch.
// All global loads (stage float4s + box float4s + label) are front-batched
// before any dependent use; labels staged via smem (stride-21 reads are
// conflict-free, gcd(21,32)=1). launch_bounds(256,6) -> <=42 regs -> 6
// blocks/SM (75% warp occupancy; was reg-limited to 5 at 48 regs).
// ---------------------------------------------------------------------------
__global__ __launch_bounds__(256, 6) void k1_main(
    const float* __restrict__ p_bboxs,
    const float* __restrict__ g_bboxs,
    const float* __restrict__ p_labels,
    const int*   __restrict__ g_labels,
    const float* __restrict__ ancs)
{
    __shared__ float sh[8][672];          // 8 warps x 32 anchors x 21 floats
    __shared__ float red_f[256];
    __shared__ float red_f2[256];
    __shared__ int   red_i[256];

    const int b     = blockIdx.y;
    const int start = blockIdx.x * CHUNK;
    const int end   = min(start + CHUNK, NN);
    const int tid   = threadIdx.x;
    const int w     = tid >> 5;
    const int l     = tid & 31;

    float lb = 0.0f, cp = 0.0f;
    int   pn = 0;

    const float* plab_b = p_labels + (size_t)b * NN * CC;

    for (int cs = start; cs < end; cs += 256) {
        const int ag = cs + w * 32;                 // this warp's anchor tile
        const bool active = (ag < end);             // tiles are always full (N%32==0)

        float4 v0, v1, v2, v3, v4, v5;
        float4 a4, g4, p4;
        int lab = 0;

        if (active) {
            // front-batch ALL global loads (10-11 LDG.128 + 1 LDG.32 in flight)
            const float4* src4 = (const float4*)(plab_b + (size_t)ag * CC);
            v0 = src4[l];
            v1 = src4[l + 32];
            v2 = src4[l + 64];
            v3 = src4[l + 96];
            v4 = src4[l + 128];
            if (l < 8) v5 = src4[160 + l];
            const int n = ag + l;
            a4 = ((const float4*)ancs)[n];
            g4 = ((const float4*)g_bboxs)[(size_t)b * NN + n];
            p4 = ((const float4*)p_bboxs)[(size_t)b * NN + n];
            lab = g_labels[(size_t)b * NN + n];

            float4* dst4 = (float4*)&sh[w][0];
            dst4[l]       = v0;
            dst4[l + 32]  = v1;
            dst4[l + 64]  = v2;
            dst4[l + 96]  = v3;
            dst4[l + 128] = v4;
            if (l < 8) dst4[160 + l] = v5;
        }
        __syncwarp();

        if (active) {
            const int n = ag + l;
            float tx = 10.0f * (g4.x - a4.x) / a4.z;
            float ty = 10.0f * (g4.y - a4.y) / a4.w;
            float tw = 5.0f * __logf(g4.z / a4.z);
            float th = 5.0f * __logf(g4.w / a4.w);
            float sl1 = sl1f(p4.x - tx) + sl1f(p4.y - ty) +
                        sl1f(p4.z - tw) + sl1f(p4.w - th);

            // cross entropy = logsumexp - x[lab]
            const float* xr = &sh[w][l * CC];
            float m = xr[0];
            #pragma unroll
            for (int c = 1; c < CC; c++) m = fmaxf(m, xr[c]);
            float s = 0.0f;
            #pragma unroll
            for (int c = 0; c < CC; c++) s += __expf(xr[c] - m);
            float ce = m + __logf(s) - xr[lab];

            const bool pos = lab > 0;
            float neg = pos ? 0.0f : ce;            // ce >= 0 -> bit order = value order
            g_bits[(size_t)b * NN + n] = __float_as_uint(neg);
            if (pos) { pn++; lb += sl1; cp += ce; }
        }
        __syncwarp();   // protect sh before next stage iteration
    }

    // deterministic block reduction
    red_f[tid] = lb; red_f2[tid] = cp; red_i[tid] = pn;
    __syncthreads();
    for (int o = 128; o > 0; o >>= 1) {
        if (tid < o) {
            red_f[tid]  += red_f[tid + o];
            red_f2[tid] += red_f2[tid + o];
            red_i[tid]  += red_i[tid + o];
        }
        __syncthreads();
    }
    if (tid == 0) {
        int idx = b * SS + blockIdx.x;
        g_part_lb[idx] = red_f[0];
        g_part_cp[idx] = red_f2[0];
        g_part_pn[idx] = red_i[0];
    }
}

// ---------------------------------------------------------------------------
// K2: one block per batch (1024 threads). Radix-select k-th largest with
// WARP-AGGREGATED histogram atomics (CE values cluster into 1-2 bins -> naive
// per-lane atomicAdd serialized on one smem address; match_any collapses a
// warp's hits on a bin to ONE atomic). Digit scan done with a parallel
// 8-step suffix-scan instead of a serial 256-iteration loop on tid 0.
// ---------------------------------------------------------------------------
__global__ __launch_bounds__(1024) void k2_select()
{
    const int b   = blockIdx.x;
    const int tid = threadIdx.x;
    const int lane = tid & 31;

    __shared__ float rf[1024];
    __shared__ float rf2[1024];
    __shared__ int   ri[1024];
    __shared__ unsigned int hist[256];
    __shared__ unsigned int sc[256];
    __shared__ unsigned int s_prefix;
    __shared__ int s_kr;

    // reduce the 33 partials
    float lb = 0.0f, cp = 0.0f; int pn = 0;
    if (tid < SS) {
        lb = g_part_lb[b * SS + tid];
        cp = g_part_cp[b * SS + tid];
        pn = g_part_pn[b * SS + tid];
    }
    rf[tid] = lb; rf2[tid] = cp; ri[tid] = pn;
    __syncthreads();
    for (int o = 512; o > 0; o >>= 1) {
        if (tid < o) { rf[tid] += rf[tid + o]; rf2[tid] += rf2[tid + o]; ri[tid] += ri[tid + o]; }
        __syncthreads();
    }
    const int   pn_t = ri[0];
    const float lb_t = rf[0];
    const float cp_t = rf2[0];
    __syncthreads();

    if (pn_t == 0) {
        if (tid == 0) {
            g_batch[b * 3 + 0] = 0.0f;
            g_batch[b * 3 + 1] = 0.0f;
            g_batch[b * 3 + 2] = 0.0f;
        }
        return;
    }

    const int k = min(3 * pn_t, NN);
    const unsigned int* vals = g_bits + (size_t)b * NN;

    // 4-pass MSB radix select for k-th largest (values are nonneg fp32 bits)
    unsigned int prefix = 0;
    int kr = k;
    for (int pass = 0; pass < 4; pass++) {
        const int shift = 24 - 8 * pass;
        if (tid < 256) hist[tid] = 0;
        __syncthreads();
        const unsigned int pmask = (pass == 0) ? 0u : (0xFFFFFFFFu << (shift + 8));
        for (int i = tid; i < NN; i += 1024) {
            unsigned int v = vals[i];
            unsigned int bin = (v >> shift) & 255u;
            bool ok = ((v & pmask) == prefix);
            unsigned int key = ok ? bin : 0x100u;
            unsigned int mask = __activemask();
            unsigned int grp = __match_any_sync(mask, key);
            if (ok && (__ffs(grp) - 1) == lane)
                atomicAdd(&hist[bin], __popc(grp));
        }
        __syncthreads();

        // suffix sums sc[d] = sum_{j>=d} hist[j]  (Hillis-Steele, 8 steps)
        if (tid < 256) sc[tid] = hist[tid];
        __syncthreads();
        for (int o = 1; o < 256; o <<= 1) {
            unsigned int add = 0;
            if (tid < 256 && tid + o < 256) add = sc[tid + o];
            __syncthreads();
            if (tid < 256) sc[tid] += add;
            __syncthreads();
        }
        // d = max{d : S(d) >= kr};  new kr = kr - S(d+1)
        if (tid < 256) {
            unsigned int s_here = sc[tid];
            unsigned int s_next = (tid < 255) ? sc[tid + 1] : 0u;
            if ((int)s_here >= kr && (int)s_next < kr) {
                s_prefix = prefix | ((unsigned int)tid << shift);
                s_kr = kr - (int)s_next;
            }
        }
        __syncthreads();
        prefix = s_prefix;
        kr = s_kr;
        __syncthreads();
    }
    const unsigned int T = prefix;

    // sum of values strictly greater than T (deterministic reduction)
    float sgt = 0.0f;
    for (int i = tid; i < NN; i += 1024) {
        unsigned int v = vals[i];
        if (v > T) sgt += __uint_as_float(v);
    }
    rf[tid] = sgt;
    __syncthreads();
    for (int o = 512; o > 0; o >>= 1) {
        if (tid < o) rf[tid] += rf[tid + o];
        __syncthreads();
    }

    if (tid == 0) {
        float topk = rf[0] + (float)kr * __uint_as_float(T);
        float loss_labels = cp_t + topk;            // positives CE + mined negatives CE
        float posf = fmaxf((float)pn_t, FP32_EPS);
        float inv = 1.0f / posf;                    // num_mask = 1 here
        g_batch[b * 3 + 0] = (lb_t + loss_labels) * inv;
        g_batch[b * 3 + 1] = lb_t * inv;
        g_batch[b * 3 + 2] = loss_labels * inv;
    }
}

// ---------------------------------------------------------------------------
// K3: mean over batches -> 3 scalars
// ---------------------------------------------------------------------------
__global__ void k3_final(float* __restrict__ out)
{
    __shared__ float r0[64], r1[64], r2[64];
    const int t = threadIdx.x;
    r0[t] = g_batch[t * 3 + 0];
    r1[t] = g_batch[t * 3 + 1];
    r2[t] = g_batch[t * 3 + 2];
    __syncthreads();
    for (int o = 32; o > 0; o >>= 1) {
        if (t < o) { r0[t] += r0[t + o]; r1[t] += r1[t + o]; r2[t] += r2[t + o]; }
        __syncthreads();
    }
    if (t == 0) {
        const float inv = 1.0f / (float)BB;
        out[0] = r0[0] * inv;
        out[1] = r1[0] * inv;
        out[2] = r2[0] * inv;
    }
}

extern "C" void kernel_launch(void* const* d_in, const int* in_sizes, int n_in,
                              void* d_out, int out_size)
{
    const float* p_bboxs  = (const float*)d_in[0];
    const float* g_bboxs  = (const float*)d_in[1];
    const float* p_labels = (const float*)d_in[2];
    const int*   g_labels = (const int*)d_in[3];
    const float* ancs     = (const float*)d_in[4];
    float* out = (float*)d_out;

    dim3 g1(SS, BB);
    k1_main<<<g1, 256>>>(p_bboxs, g_bboxs, p_labels, g_labels, ancs);
    k2_select<<<BB, 1024>>>();
    k3_final<<<1, 64>>>(out);
}

// round 7
// speedup vs baseline: 1.3105x; 1.3105x over previous
#include <cuda_runtime.h>
#include <math.h>

#define BB 64
#define NN 16800
#define CC 21
#define CHUNK 512
#define SS 33          // ceil(16800/512)
#define NV4 4200       // NN / 4
#define FP32_EPS 1.1920928955078125e-07f

// scratch (no cudaMalloc allowed)
__device__ unsigned int g_bits[BB * NN];      // labels_neg as fp32 bits (all >= +0)
__device__ float g_part_lb[BB * SS];
__device__ float g_part_cp[BB * SS];
__device__ int   g_part_pn[BB * SS];
__device__ float g_batch[BB * 3];

__device__ __forceinline__ float sl1f(float d) {
    float a = fabsf(d);
    return a < 1.0f ? 0.5f * d * d : a - 0.5f;
}

// ---------------------------------------------------------------------------
// K1: stream everything once (load->STS staging, fast-math intrinsics).
// ---------------------------------------------------------------------------
__global__ __launch_bounds__(256) void k1_main(
    const float* __restrict__ p_bboxs,
    const float* __restrict__ g_bboxs,
    const float* __restrict__ p_labels,
    const int*   __restrict__ g_labels,
    const float* __restrict__ ancs)
{
    __shared__ float sh[8][672];          // 8 warps x 32 anchors x 21 floats
    __shared__ float red_f[256];
    __shared__ float red_f2[256];
    __shared__ int   red_i[256];

    const int b     = blockIdx.y;
    const int start = blockIdx.x * CHUNK;
    const int end   = min(start + CHUNK, NN);
    const int tid   = threadIdx.x;
    const int w     = tid >> 5;
    const int l     = tid & 31;

    float lb = 0.0f, cp = 0.0f;
    int   pn = 0;

    const float* plab_b = p_labels + (size_t)b * NN * CC;

    for (int cs = start; cs < end; cs += 256) {
        const int ag = cs + w * 32;
        const bool active = (ag < end);     // tiles always full (NN % 32 == 0)

        if (active) {
            const float4* src4 = (const float4*)(plab_b + (size_t)ag * CC);
            float4* dst4 = (float4*)&sh[w][0];
            #pragma unroll
            for (int j = 0; j < 5; j++)
                dst4[l + 32 * j] = src4[l + 32 * j];
            if (l < 8)
                dst4[160 + l] = src4[160 + l];
        }
        __syncwarp();

        if (active) {
            const int n = ag + l;
            float4 a4 = ((const float4*)ancs)[n];
            float4 g4 = ((const float4*)g_bboxs)[(size_t)b * NN + n];
            float4 p4 = ((const float4*)p_bboxs)[(size_t)b * NN + n];
            float tx = 10.0f * (g4.x - a4.x) / a4.z;
            float ty = 10.0f * (g4.y - a4.y) / a4.w;
            float tw = 5.0f * __logf(g4.z / a4.z);
            float th = 5.0f * __logf(g4.w / a4.w);
            float sl1 = sl1f(p4.x - tx) + sl1f(p4.y - ty) +
                        sl1f(p4.z - tw) + sl1f(p4.w - th);

            const int lab = g_labels[(size_t)b * NN + n];

            const float* xr = &sh[w][l * CC];
            float m = xr[0];
            #pragma unroll
            for (int c = 1; c < CC; c++) m = fmaxf(m, xr[c]);
            float s = 0.0f;
            #pragma unroll
            for (int c = 0; c < CC; c++) s += __expf(xr[c] - m);
            float ce = m + __logf(s) - xr[lab];

            const bool pos = lab > 0;
            float neg = pos ? 0.0f : ce;    // ce >= 0 -> bit order = value order
            g_bits[(size_t)b * NN + n] = __float_as_uint(neg);
            if (pos) { pn++; lb += sl1; cp += ce; }
        }
        __syncwarp();
    }

    red_f[tid] = lb; red_f2[tid] = cp; red_i[tid] = pn;
    __syncthreads();
    for (int o = 128; o > 0; o >>= 1) {
        if (tid < o) {
            red_f[tid]  += red_f[tid + o];
            red_f2[tid] += red_f2[tid + o];
            red_i[tid]  += red_i[tid + o];
        }
        __syncthreads();
    }
    if (tid == 0) {
        int idx = b * SS + blockIdx.x;
        g_part_lb[idx] = red_f[0];
        g_part_cp[idx] = red_f2[0];
        g_part_pn[idx] = red_i[0];
    }
}

// ---------------------------------------------------------------------------
// K2: one block per batch, 1024 threads. Radix top-k-sum with digits
// 12/10/10, warp-aggregated histogram atomics, warp-local suffix scans,
// progressive fused ">" sums, and uint4-vectorized value scans.
// ---------------------------------------------------------------------------

// process one value within the scan loop (warp-aggregated histogram update)
#define K2_PROC(vval, vld) do {                                               \
    unsigned int v = (vval);                                                  \
    bool ok; unsigned int bin;                                                \
    if (pass == 0) {                                                          \
        ok = (vld); bin = v >> 20;                                            \
    } else if (pass == 1) {                                                   \
        unsigned int t12 = v >> 20;                                           \
        if ((vld) && t12 > j0) fsum += __uint_as_float(v);                    \
        ok = (vld) && (t12 == j0); bin = (v >> 10) & 1023u;                   \
    } else {                                                                  \
        unsigned int t12 = v >> 20;                                           \
        unsigned int n10 = (v >> 10) & 1023u;                                 \
        if ((vld) && t12 == j0 && n10 > j1) fsum += __uint_as_float(v);       \
        ok = (vld) && (t12 == j0) && (n10 == j1); bin = v & 1023u;            \
    }                                                                         \
    unsigned int key = ok ? bin : 0xFFFFu;                                    \
    unsigned int grp = __match_any_sync(0xFFFFFFFFu, key);                    \
    if (ok && ((__ffs(grp) - 1) == lane))                                     \
        atomicAdd(&hist[bin], (unsigned int)__popc(grp));                     \
} while (0)

__global__ __launch_bounds__(1024) void k2_select()
{
    const int b    = blockIdx.x;
    const int tid  = threadIdx.x;
    const int lane = tid & 31;
    const int wid  = tid >> 5;

    __shared__ unsigned int hist[4096];
    __shared__ unsigned int chunk[32];
    __shared__ float warr[32];
    __shared__ float warr2[32];
    __shared__ int   wari[32];
    __shared__ int s_digit, s_kr;
    __shared__ float s_lb, s_cp;
    __shared__ int s_pn;

    // ---- reduce the 33 per-chunk partials ----
    {
        float lbv = 0.0f, cpv = 0.0f; int pnv = 0;
        if (tid < SS) {
            lbv = g_part_lb[b * SS + tid];
            cpv = g_part_cp[b * SS + tid];
            pnv = g_part_pn[b * SS + tid];
        }
        if (tid < 64) {
            #pragma unroll
            for (int o = 16; o > 0; o >>= 1) {
                lbv += __shfl_down_sync(0xFFFFFFFFu, lbv, o);
                cpv += __shfl_down_sync(0xFFFFFFFFu, cpv, o);
                pnv += __shfl_down_sync(0xFFFFFFFFu, pnv, o);
            }
            if (lane == 0) { warr[wid] = lbv; warr2[wid] = cpv; wari[wid] = pnv; }
        }
        __syncthreads();
        if (tid == 0) {
            s_lb = warr[0] + warr[1];
            s_cp = warr2[0] + warr2[1];
            s_pn = wari[0] + wari[1];
        }
        __syncthreads();
    }
    const int   pn_t = s_pn;
    const float lb_t = s_lb;
    const float cp_t = s_cp;

    if (pn_t == 0) {
        if (tid == 0) {
            g_batch[b * 3 + 0] = 0.0f;
            g_batch[b * 3 + 1] = 0.0f;
            g_batch[b * 3 + 2] = 0.0f;
        }
        return;
    }

    const int k = min(3 * pn_t, NN);
    const uint4* vals4 = (const uint4*)(g_bits + (size_t)b * NN);  // 16B aligned

    float fsum = 0.0f;        // fused sum of values strictly above evolving prefix
    int kr = k;
    unsigned int j0 = 0, j1 = 0;

    #pragma unroll 1
    for (int pass = 0; pass < 3; pass++) {
        // zero histogram
        #pragma unroll
        for (int j = 0; j < 4; j++) hist[tid + 1024 * j] = 0u;
        __syncthreads();

        // vectorized scan: 5 iterations of LDG.128 per thread
        #pragma unroll 1
        for (int base = 0; base < 5120; base += 1024) {
            int i = base + tid;
            bool valid = i < NV4;
            uint4 vv = make_uint4(0u, 0u, 0u, 0u);
            if (valid) vv = vals4[i];
            K2_PROC(vv.x, valid);
            K2_PROC(vv.y, valid);
            K2_PROC(vv.z, valid);
            K2_PROC(vv.w, valid);
        }
        __syncthreads();

        // two-level warp-local digit pick over 4096 bins:
        // level 1: thread t sums bins [4t,4t+4); warp w owns bins [128w,128w+128)
        {
            unsigned int s4 = hist[4 * tid] + hist[4 * tid + 1] +
                              hist[4 * tid + 2] + hist[4 * tid + 3];
            #pragma unroll
            for (int o = 16; o > 0; o >>= 1) s4 += __shfl_down_sync(0xFFFFFFFFu, s4, o);
            if (lane == 0) chunk[wid] = s4;
        }
        __syncthreads();
        if (wid == 0) {
            // suffix over 32 chunks
            unsigned int suf = chunk[lane];
            #pragma unroll
            for (int o = 1; o < 32; o <<= 1) {
                unsigned int t = __shfl_down_sync(0xFFFFFFFFu, suf, o);
                if (lane + o < 32) suf += t;
            }
            unsigned int suf_next = __shfl_down_sync(0xFFFFFFFFu, suf, 1);
            if (lane == 31) suf_next = 0u;
            bool hit = ((int)suf >= kr) && ((int)suf_next < kr);
            unsigned int m = __ballot_sync(0xFFFFFFFFu, hit);
            int src = __ffs(m) - 1;
            int cstar = src;
            int basec = (int)__shfl_sync(0xFFFFFFFFu, suf_next, src);
            // level 2: within chunk cstar (128 bins), lane owns 4 contiguous bins
            int b0 = cstar * 128 + lane * 4;
            unsigned int h0 = hist[b0], h1 = hist[b0 + 1],
                         h2 = hist[b0 + 2], h3 = hist[b0 + 3];
            unsigned int lsum = h0 + h1 + h2 + h3;
            unsigned int lsuf = lsum;
            #pragma unroll
            for (int o = 1; o < 32; o <<= 1) {
                unsigned int t = __shfl_down_sync(0xFFFFFFFFu, lsuf, o);
                if (lane + o < 32) lsuf += t;
            }
            unsigned int nx = __shfl_down_sync(0xFFFFFFFFu, lsuf, 1);
            if (lane == 31) nx = 0u;
            int above = basec + (int)nx;     // count strictly above this lane's 4 bins
            if (above < kr && kr <= above + (int)lsum) {
                int r = above;
                int digit; int below;
                if (r + (int)h3 >= kr)       { digit = b0 + 3; below = r; }
                else { r += (int)h3;
                  if (r + (int)h2 >= kr)     { digit = b0 + 2; below = r; }
                  else { r += (int)h2;
                    if (r + (int)h1 >= kr)   { digit = b0 + 1; below = r; }
                    else { r += (int)h1;       digit = b0;     below = r; } } }
                s_digit = digit;
                s_kr = kr - below;
            }
        }
        __syncthreads();
        if (pass == 0)      j0 = (unsigned int)s_digit;
        else if (pass == 1) j1 = (unsigned int)s_digit;
        kr = s_kr;
        __syncthreads();
    }
    const unsigned int j2 = (unsigned int)s_digit;
    const unsigned int Tbits = (j0 << 20) | (j1 << 10) | j2;

    // final-pass histogram bins fully determine the value:
    // add sum over bins > j2 of count*value (thread t owns bin t)
    if ((unsigned int)tid > j2) {
        unsigned int c = hist[tid];
        if (c) fsum += (float)c * __uint_as_float((j0 << 20) | (j1 << 10) | (unsigned int)tid);
    }

    // deterministic block reduction of fsum
    #pragma unroll
    for (int o = 16; o > 0; o >>= 1) fsum += __shfl_down_sync(0xFFFFFFFFu, fsum, o);
    if (lane == 0) warr[wid] = fsum;
    __syncthreads();
    if (wid == 0) {
        float x = warr[lane];
        #pragma unroll
        for (int o = 16; o > 0; o >>= 1) x += __shfl_down_sync(0xFFFFFFFFu, x, o);
        if (lane == 0) {
            float topk = x + (float)kr * __uint_as_float(Tbits);
            float loss_labels = cp_t + topk;
            float posf = fmaxf((float)pn_t, FP32_EPS);
            float inv = 1.0f / posf;
            g_batch[b * 3 + 0] = (lb_t + loss_labels) * inv;
            g_batch[b * 3 + 1] = lb_t * inv;
            g_batch[b * 3 + 2] = loss_labels * inv;
        }
    }
}

// ---------------------------------------------------------------------------
// K3: mean over batches -> 3 scalars
// ---------------------------------------------------------------------------
__global__ void k3_final(float* __restrict__ out)
{
    __shared__ float r0[64], r1[64], r2[64];
    const int t = threadIdx.x;
    r0[t] = g_batch[t * 3 + 0];
    r1[t] = g_batch[t * 3 + 1];
    r2[t] = g_batch[t * 3 + 2];
    __syncthreads();
    for (int o = 32; o > 0; o >>= 1) {
        if (t < o) { r0[t] += r0[t + o]; r1[t] += r1[t + o]; r2[t] += r2[t + o]; }
        __syncthreads();
    }
    if (t == 0) {
        const float inv = 1.0f / (float)BB;
        out[0] = r0[0] * inv;
        out[1] = r1[0] * inv;
        out[2] = r2[0] * inv;
    }
}

extern "C" void kernel_launch(void* const* d_in, const int* in_sizes, int n_in,
                              void* d_out, int out_size)
{
    const float* p_bboxs  = (const float*)d_in[0];
    const float* g_bboxs  = (const float*)d_in[1];
    const float* p_labels = (const float*)d_in[2];
    const int*   g_labels = (const int*)d_in[3];
    const float* ancs     = (const float*)d_in[4];
    float* out = (float*)d_out;

    dim3 g1(SS, BB);
    k1_main<<<g1, 256>>>(p_bboxs, g_bboxs, p_labels, g_labels, ancs);
    k2_select<<<BB, 1024>>>();
    k3_final<<<1, 64>>>(out);
}

// round 14
// speedup vs baseline: 1.3277x; 1.0131x over previous
#include <cuda_runtime.h>
#include <math.h>

#define BB 64
#define NN 16800
#define CC 21
#define SS 66          // units of 256 anchors: ceil(16800/256)
#define NV4 4200       // NN / 4
#define LIST_CAP 6144
#define TINY_CAP 512
#define FP32_EPS 1.1920928955078125e-07f

// scratch (no cudaMalloc allowed)
__device__ unsigned int g_bits[BB * NN];      // labels_neg as fp32 bits (all >= +0)
__device__ float g_part_lb[BB * SS];
__device__ float g_part_cp[BB * SS];
__device__ int   g_part_pn[BB * SS];
__device__ float g_batch[BB * 3];

__device__ __forceinline__ float sl1f(float d) {
    float a = fabsf(d);
    return a < 1.0f ? 0.5f * d * d : a - 0.5f;
}

// ---------------------------------------------------------------------------
// K1: one block = ONE 256-anchor unit of one batch (no inner loop).
// grid = 66 x 64 = 4224 blocks -> 4.76 waves at 6 blocks/SM (95% wave fill;
// the old 2112-block grid hit 2.38 waves = 79% fill, which is why higher
// occupancy REGRESSED K1 in R7). Staging + compute unchanged from the
// measured-good structure.
// ---------------------------------------------------------------------------
__global__ __launch_bounds__(256) void k1_main(
    const float* __restrict__ p_bboxs,
    const float* __restrict__ g_bboxs,
    const float* __restrict__ p_labels,
    const int*   __restrict__ g_labels,
    const float* __restrict__ ancs)
{
    __shared__ float sh[8][672];          // 8 warps x 32 anchors x 21 floats
    __shared__ float red_f[256];
    __shared__ float red_f2[256];
    __shared__ int   red_i[256];

    const int b   = blockIdx.y;
    const int tid = threadIdx.x;
    const int w   = tid >> 5;
    const int l   = tid & 31;

    const int ag = blockIdx.x * 256 + w * 32;   // this warp's 32-anchor tile
    const bool active = (ag < NN);              // tiles always full (NN % 32 == 0)

    float lb = 0.0f, cp = 0.0f;
    int   pn = 0;

    const float* plab_b = p_labels + (size_t)b * NN * CC;

    if (active) {
        const float4* src4 = (const float4*)(plab_b + (size_t)ag * CC);
        float4* dst4 = (float4*)&sh[w][0];
        #pragma unroll
        for (int j = 0; j < 5; j++)
            dst4[l + 32 * j] = src4[l + 32 * j];
        if (l < 8)
            dst4[160 + l] = src4[160 + l];
    }
    __syncwarp();

    if (active) {
        const int n = ag + l;
        float4 a4 = ((const float4*)ancs)[n];
        float4 g4 = ((const float4*)g_bboxs)[(size_t)b * NN + n];
        float4 p4 = ((const float4*)p_bboxs)[(size_t)b * NN + n];
        float tx = 10.0f * (g4.x - a4.x) / a4.z;
        float ty = 10.0f * (g4.y - a4.y) / a4.w;
        float tw = 5.0f * __logf(g4.z / a4.z);
        float th = 5.0f * __logf(g4.w / a4.w);
        float sl1 = sl1f(p4.x - tx) + sl1f(p4.y - ty) +
                    sl1f(p4.z - tw) + sl1f(p4.w - th);

        const int lab = g_labels[(size_t)b * NN + n];

        const float* xr = &sh[w][l * CC];
        float m = xr[0];
        #pragma unroll
        for (int c = 1; c < CC; c++) m = fmaxf(m, xr[c]);
        float s = 0.0f;
        #pragma unroll
        for (int c = 0; c < CC; c++) s += __expf(xr[c] - m);
        float ce = m + __logf(s) - xr[lab];

        const bool pos = lab > 0;
        float neg = pos ? 0.0f : ce;        // ce >= 0 -> bit order = value order
        g_bits[(size_t)b * NN + n] = __float_as_uint(neg);
        if (pos) { pn = 1; lb = sl1; cp = ce; }
    }

    // deterministic block reduction
    red_f[tid] = lb; red_f2[tid] = cp; red_i[tid] = pn;
    __syncthreads();
    for (int o = 128; o > 0; o >>= 1) {
        if (tid < o) {
            red_f[tid]  += red_f[tid + o];
            red_f2[tid] += red_f2[tid + o];
            red_i[tid]  += red_i[tid + o];
        }
        __syncthreads();
    }
    if (tid == 0) {
        int idx = b * SS + blockIdx.x;
        g_part_lb[idx] = red_f[0];
        g_part_cp[idx] = red_f2[0];
        g_part_pn[idx] = red_i[0];
    }
}

// ---------------------------------------------------------------------------
// digit pick over 2048-bin histogram: finds d* = max{d : sum_{j>=d} h[j] >= kr}
// and kr' = kr - sum_{j>d*} h[j]. All threads must call (contains barriers).
// ---------------------------------------------------------------------------
__device__ __forceinline__ void pick2048(
    const unsigned int* hist, unsigned int* chunkv,
    int* s_w, int* s_base, int* s_digit, int* s_kr,
    int kr, int tid, int lane, int wid)
{
    unsigned int ps = hist[2 * tid] + hist[2 * tid + 1];   // pair sum
    unsigned int ws = ps;
    #pragma unroll
    for (int o = 16; o > 0; o >>= 1) ws += __shfl_down_sync(0xFFFFFFFFu, ws, o);
    if (lane == 0) chunkv[wid] = ws;                       // warp total (64 bins)
    __syncthreads();
    if (wid == 0) {
        unsigned int suf = chunkv[lane];
        #pragma unroll
        for (int o = 1; o < 32; o <<= 1) {
            unsigned int t = __shfl_down_sync(0xFFFFFFFFu, suf, o);
            if (lane + o < 32) suf += t;
        }
        unsigned int sufn = __shfl_down_sync(0xFFFFFFFFu, suf, 1);
        if (lane == 31) sufn = 0u;
        bool hit = ((int)suf >= kr) && ((int)sufn < kr);
        unsigned int m = __ballot_sync(0xFFFFFFFFu, hit);
        int src = __ffs(m) - 1;
        if (lane == 0) *s_w = src;
        if (lane == src) *s_base = (int)sufn;
    }
    __syncthreads();
    if (wid == *s_w) {
        // this warp's lane <-> pair index 32*wid + lane, pair sum = ps
        unsigned int lsuf = ps;
        #pragma unroll
        for (int o = 1; o < 32; o <<= 1) {
            unsigned int t = __shfl_down_sync(0xFFFFFFFFu, lsuf, o);
            if (lane + o < 32) lsuf += t;
        }
        unsigned int ln = __shfl_down_sync(0xFFFFFFFFu, lsuf, 1);
        if (lane == 31) ln = 0u;
        int above = *s_base + (int)ln;     // count in bins strictly above this pair
        if (above < kr && kr <= above + (int)ps) {
            int bhi = 2 * (32 * wid + lane) + 1;
            unsigned int h1 = hist[bhi];
            if (above + (int)h1 >= kr) { *s_digit = bhi;     *s_kr = kr - above; }
            else                       { *s_digit = bhi - 1; *s_kr = kr - above - (int)h1; }
        }
    }
    __syncthreads();
}

// ---------------------------------------------------------------------------
// K2: one block per batch, 1024 threads. ONE match-aggregated coarse pass,
// then cheap compaction + uniform-bin refinement on the compacted subset.
// ---------------------------------------------------------------------------
__global__ __launch_bounds__(1024) void k2_select()
{
    const int b    = blockIdx.x;
    const int tid  = threadIdx.x;
    const int lane = tid & 31;
    const int wid  = tid >> 5;

    __shared__ unsigned int hist[2048];
    __shared__ unsigned int chunkv[32];
    __shared__ unsigned int list[LIST_CAP];
    __shared__ unsigned int tinyv[TINY_CAP];
    __shared__ float warr[32];
    __shared__ float warr2[32];
    __shared__ int   wari[32];
    __shared__ int s_digit, s_kr, s_w, s_base;
    __shared__ float s_lb, s_cp;
    __shared__ int s_pn;
    __shared__ int s_nc, s_nt;
    __shared__ unsigned int s_T;
    __shared__ float s_sgt_tiny;
    __shared__ int s_cgt_tiny;

    // ---- reduce the 66 per-unit partials (first 4 warps) ----
    {
        float lbv = 0.0f, cpv = 0.0f; int pnv = 0;
        if (tid < SS) {
            lbv = g_part_lb[b * SS + tid];
            cpv = g_part_cp[b * SS + tid];
            pnv = g_part_pn[b * SS + tid];
        }
        if (tid < 128) {
            #pragma unroll
            for (int o = 16; o > 0; o >>= 1) {
                lbv += __shfl_down_sync(0xFFFFFFFFu, lbv, o);
                cpv += __shfl_down_sync(0xFFFFFFFFu, cpv, o);
                pnv += __shfl_down_sync(0xFFFFFFFFu, pnv, o);
            }
            if (lane == 0) { warr[wid] = lbv; warr2[wid] = cpv; wari[wid] = pnv; }
        }
        __syncthreads();
        if (tid == 0) {
            s_lb = warr[0] + warr[1] + warr[2] + warr[3];
            s_cp = warr2[0] + warr2[1] + warr2[2] + warr2[3];
            s_pn = wari[0] + wari[1] + wari[2] + wari[3];
        }
        __syncthreads();
    }
    const int   pn_t = s_pn;
    const float lb_t = s_lb;
    const float cp_t = s_cp;

    if (pn_t == 0) {
        if (tid == 0) {
            g_batch[b * 3 + 0] = 0.0f;
            g_batch[b * 3 + 1] = 0.0f;
            g_batch[b * 3 + 2] = 0.0f;
        }
        return;
    }

    const int k = min(3 * pn_t, NN);
    const uint4* vals4 = (const uint4*)(g_bits + (size_t)b * NN);  // 16B aligned

    // ---- P1: 2048-bin coarse histogram of v>>20 (match-aggregated) ----
    hist[tid] = 0u; hist[tid + 1024] = 0u;
    if (tid == 0) { s_nc = 0; s_nt = 0; }
    __syncthreads();
    for (int base = 0; base < 5120; base += 1024) {
        int i = base + tid;
        bool valid = i < NV4;
        uint4 vv = valid ? vals4[i] : make_uint4(0u, 0u, 0u, 0u);
        #define P1V(v) do { unsigned int bin = (v) >> 20;                     \
            unsigned int key = valid ? bin : 0xFFFFu;                         \
            unsigned int grp = __match_any_sync(0xFFFFFFFFu, key);            \
            if (valid && ((__ffs(grp) - 1) == lane))                          \
                atomicAdd(&hist[bin], (unsigned int)__popc(grp)); } while (0)
        P1V(vv.x); P1V(vv.y); P1V(vv.z); P1V(vv.w);
        #undef P1V
    }
    __syncthreads();
    pick2048(hist, chunkv, &s_w, &s_base, &s_digit, &s_kr, k, tid, lane, wid);
    const unsigned int j0 = (unsigned int)s_digit;
    const int kr1 = s_kr;
    __syncthreads();

    // ---- P2: register sums for bins > j0; compact bin==j0 into list ----
    float fs = 0.0f; int cg = 0;
    for (int base = 0; base < 5120; base += 1024) {
        int i = base + tid;
        bool valid = i < NV4;
        uint4 vv = valid ? vals4[i] : make_uint4(0u, 0u, 0u, 0u);
        #define P2V(v) do { unsigned int bv = (v); unsigned int bin = bv >> 20; \
            if (valid && bin > j0) { fs += __uint_as_float(bv); cg++; }       \
            bool pred = valid && (bin == j0);                                 \
            unsigned int mk = __ballot_sync(0xFFFFFFFFu, pred);               \
            if (mk) { int ldr = __ffs(mk) - 1; int bs = 0;                    \
                if (lane == ldr) bs = atomicAdd(&s_nc, __popc(mk));           \
                bs = __shfl_sync(0xFFFFFFFFu, bs, ldr);                       \
                if (pred) { int pos = bs + __popc(mk & ((1u << lane) - 1u));  \
                    if (pos < LIST_CAP) list[pos] = bv; } } } while (0)
        P2V(vv.x); P2V(vv.y); P2V(vv.z); P2V(vv.w);
        #undef P2V
    }
    __syncthreads();
    const int Nc = min(s_nc, LIST_CAP);
    const int nit = (Nc + 1023) >> 10;

    // ---- P3: refine over list with uniform bins on bits [9:20) ----
    hist[tid] = 0u; hist[tid + 1024] = 0u;
    __syncthreads();
    for (int it = 0; it < nit; it++) {
        int i = it * 1024 + tid;
        if (i < Nc) atomicAdd(&hist[(list[i] >> 9) & 0x7FFu], 1u);
    }
    __syncthreads();
    pick2048(hist, chunkv, &s_w, &s_base, &s_digit, &s_kr, kr1, tid, lane, wid);
    const unsigned int j1 = (unsigned int)s_digit;
    const int kr2 = s_kr;
    __syncthreads();

    // ---- P4: sums for l2 > j1; push 23-bit-prefix matches into tiny list ----
    for (int it = 0; it < nit; it++) {
        int i = it * 1024 + tid;
        if (i < Nc) {
            unsigned int u = list[i];
            unsigned int l2 = (u >> 9) & 0x7FFu;
            if (l2 > j1) { fs += __uint_as_float(u); cg++; }
            else if (l2 == j1) {
                int p = atomicAdd(&s_nt, 1);
                if (p < TINY_CAP) tinyv[p] = u;
            }
        }
    }
    __syncthreads();

    // ---- warp 0: exact kr2-th largest T among tiny; tiny >T sums ----
    if (wid == 0) {
        int nt = min(s_nt, TINY_CAP);
        unsigned int Tc = 0u;
        for (int i = lane; i < nt; i += 32) {
            unsigned int u = tinyv[i];
            int g = 0, e = 0;
            for (int j = 0; j < nt; j++) {
                unsigned int w2 = tinyv[j];
                g += (w2 > u); e += (w2 == u);
            }
            if (g < kr2 && kr2 <= g + e) Tc = u;
        }
        #pragma unroll
        for (int o = 16; o > 0; o >>= 1) {
            unsigned int t = __shfl_down_sync(0xFFFFFFFFu, Tc, o);
            Tc = Tc > t ? Tc : t;
        }
        Tc = __shfl_sync(0xFFFFFFFFu, Tc, 0);
        float st = 0.0f; int ct = 0;
        for (int i = lane; i < nt; i += 32) {
            unsigned int u = tinyv[i];
            if (u > Tc) { st += __uint_as_float(u); ct++; }
        }
        #pragma unroll
        for (int o = 16; o > 0; o >>= 1) {
            st += __shfl_down_sync(0xFFFFFFFFu, st, o);
            ct += __shfl_down_sync(0xFFFFFFFFu, ct, o);
        }
        if (lane == 0) { s_T = Tc; s_sgt_tiny = st; s_cgt_tiny = ct; }
    }
    __syncthreads();

    // ---- final: reduce fs/cg, combine ----
    #pragma unroll
    for (int o = 16; o > 0; o >>= 1) {
        fs += __shfl_down_sync(0xFFFFFFFFu, fs, o);
        cg += __shfl_down_sync(0xFFFFFFFFu, cg, o);
    }
    if (lane == 0) { warr[wid] = fs; wari[wid] = cg; }
    __syncthreads();
    if (wid == 0) {
        float x = warr[lane]; int c = wari[lane];
        #pragma unroll
        for (int o = 16; o > 0; o >>= 1) {
            x += __shfl_down_sync(0xFFFFFFFFu, x, o);
            c += __shfl_down_sync(0xFFFFFFFFu, c, o);
        }
        if (lane == 0) {
            float T = __uint_as_float(s_T);
            float sgt = x + s_sgt_tiny;
            int   cgt = c + s_cgt_tiny;
            float topk = sgt + (float)(k - cgt) * T;
            float loss_labels = cp_t + topk;
            float posf = fmaxf((float)pn_t, FP32_EPS);
            float inv = 1.0f / posf;
            g_batch[b * 3 + 0] = (lb_t + loss_labels) * inv;
            g_batch[b * 3 + 1] = lb_t * inv;
            g_batch[b * 3 + 2] = loss_labels * inv;
        }
    }
}

// ---------------------------------------------------------------------------
// K3: mean over batches -> 3 scalars
// ---------------------------------------------------------------------------
__global__ void k3_final(float* __restrict__ out)
{
    __shared__ float r0[64], r1[64], r2[64];
    const int t = threadIdx.x;
    r0[t] = g_batch[t * 3 + 0];
    r1[t] = g_batch[t * 3 + 1];
    r2[t] = g_batch[t * 3 + 2];
    __syncthreads();
    for (int o = 32; o > 0; o >>= 1) {
        if (t < o) { r0[t] += r0[t + o]; r1[t] += r1[t + o]; r2[t] += r2[t + o]; }
        __syncthreads();
    }
    if (t == 0) {
        const float inv = 1.0f / (float)BB;
        out[0] = r0[0] * inv;
        out[1] = r1[0] * inv;
        out[2] = r2[0] * inv;
    }
}

extern "C" void kernel_launch(void* const* d_in, const int* in_sizes, int n_in,
                              void* d_out, int out_size)
{
    const float* p_bboxs  = (const float*)d_in[0];
    const float* g_bboxs  = (const float*)d_in[1];
    const float* p_labels = (const float*)d_in[2];
    const int*   g_labels = (const int*)d_in[3];
    const float* ancs     = (const float*)d_in[4];
    float* out = (float*)d_out;

    dim3 g1(SS, BB);
    k1_main<<<g1, 256>>>(p_bboxs, g_bboxs, p_labels, g_labels, ancs);
    k2_select<<<BB, 1024>>>();
    k3_final<<<1, 64>>>(out);
}